// round 1
// baseline (speedup 1.0000x reference)
#include <cuda_runtime.h>
#include <math.h>

// Problem constants
#define PP 20
#define NN 1024
#define DD 512
#define TPB 128          // threads per block in main kernel; each thread owns 4 d-columns
#define NWARP (TPB / 32)
#define EPS 1e-8f

// Global accumulators (allocation-free scratch)
__device__ float gS[DD];     // S[d] = sum_n an[n][d]
__device__ float gT[DD];     // T[d] = sum_{p,n} zn[p][n][d]
__device__ float gDiag;      // sum_{p,n} zn[p][n] . an[n]

__global__ void init_kernel() {
    int t = threadIdx.x;
    if (t < DD) { gS[t] = 0.0f; gT[t] = 0.0f; }
    if (t == 0) gDiag = 0.0f;
}

// One block per column n. Loads z[:, n, :] (20 x 512 floats) as float4,
// computes avg, ||avg||, 20 row norms, 20 dots z_p.avg via 41 block reductions,
// then accumulates an, sum_p zn_p, and the diagonal scalar.
__global__ __launch_bounds__(TPB) void main_kernel(const float* __restrict__ z) {
    const int n    = blockIdx.x;
    const int t    = threadIdx.x;
    const int wid  = t >> 5;
    const int lane = t & 31;
    const int d0   = t * 4;

    // ---- load 20 rows of this column group (fully coalesced LDG.128) ----
    float4 zp[PP];
    const float4* base =
        reinterpret_cast<const float4*>(z + (size_t)n * DD) + t;
    #pragma unroll
    for (int p = 0; p < PP; ++p)
        zp[p] = base[(size_t)p * (NN * DD / 4)];

    // ---- avg over P ----
    float4 avg = make_float4(0.f, 0.f, 0.f, 0.f);
    #pragma unroll
    for (int p = 0; p < PP; ++p) {
        avg.x += zp[p].x; avg.y += zp[p].y;
        avg.z += zp[p].z; avg.w += zp[p].w;
    }
    const float invP = 1.0f / (float)PP;
    avg.x *= invP; avg.y *= invP; avg.z *= invP; avg.w *= invP;

    // ---- 41 per-thread partial sums ----
    // s[0]      : ||avg||^2
    // s[1+p]    : ||z_p||^2
    // s[21+p]   : z_p . avg
    float s[41];
    s[0] = avg.x * avg.x + avg.y * avg.y + avg.z * avg.z + avg.w * avg.w;
    #pragma unroll
    for (int p = 0; p < PP; ++p) {
        s[1 + p]  = zp[p].x * zp[p].x + zp[p].y * zp[p].y
                  + zp[p].z * zp[p].z + zp[p].w * zp[p].w;
        s[21 + p] = zp[p].x * avg.x + zp[p].y * avg.y
                  + zp[p].z * avg.z + zp[p].w * avg.w;
    }

    // ---- warp butterfly reduce all 41 sums ----
    #pragma unroll
    for (int i = 0; i < 41; ++i) {
        float v = s[i];
        #pragma unroll
        for (int o = 16; o > 0; o >>= 1)
            v += __shfl_xor_sync(0xffffffffu, v, o);
        s[i] = v;
    }

    __shared__ float wp[41][NWARP];
    if (lane == 0) {
        #pragma unroll
        for (int i = 0; i < 41; ++i) wp[i][wid] = s[i];
    }
    __syncthreads();

    __shared__ float fin[41];       // block-final sums
    __shared__ float derived[21];   // [0]=1/max(||avg||,eps), [1+p]=1/max(||z_p||,eps)
    if (t < 41) {
        float v = 0.f;
        #pragma unroll
        for (int w = 0; w < NWARP; ++w) v += wp[t][w];
        fin[t] = v;
        if (t <= 20) derived[t] = 1.0f / fmaxf(sqrtf(v), EPS);
    }
    __syncthreads();

    const float inv_avg = derived[0];

    // an contribution and zn-sum contribution for this thread's 4 columns
    float an0 = avg.x * inv_avg, an1 = avg.y * inv_avg;
    float an2 = avg.z * inv_avg, an3 = avg.w * inv_avg;

    float zn0 = 0.f, zn1 = 0.f, zn2 = 0.f, zn3 = 0.f;
    #pragma unroll
    for (int p = 0; p < PP; ++p) {
        float ip = derived[1 + p];
        zn0 += zp[p].x * ip; zn1 += zp[p].y * ip;
        zn2 += zp[p].z * ip; zn3 += zp[p].w * ip;
    }

    atomicAdd(&gS[d0 + 0], an0);
    atomicAdd(&gS[d0 + 1], an1);
    atomicAdd(&gS[d0 + 2], an2);
    atomicAdd(&gS[d0 + 3], an3);
    atomicAdd(&gT[d0 + 0], zn0);
    atomicAdd(&gT[d0 + 1], zn1);
    atomicAdd(&gT[d0 + 2], zn2);
    atomicAdd(&gT[d0 + 3], zn3);

    if (t == 0) {
        // diag_n = sum_p (z_p . avg) * inv_avg * inv_p
        float dg = 0.f;
        #pragma unroll
        for (int p = 0; p < PP; ++p)
            dg += fin[21 + p] * derived[1 + p];
        atomicAdd(&gDiag, dg * inv_avg);
    }
}

// Single block: result = (T.S - diag) / count - 1
__global__ void final_kernel(float* __restrict__ out) {
    const int t    = threadIdx.x;  // 512 threads, one per d
    const int wid  = t >> 5;
    const int lane = t & 31;

    float v = gS[t] * gT[t];
    #pragma unroll
    for (int o = 16; o > 0; o >>= 1)
        v += __shfl_xor_sync(0xffffffffu, v, o);

    __shared__ float w[16];
    if (lane == 0) w[wid] = v;
    __syncthreads();

    if (t == 0) {
        float ts = 0.f;
        #pragma unroll
        for (int i = 0; i < 16; ++i) ts += w[i];
        const double count = 20.0 * 1024.0 * 1023.0;
        out[0] = (float)(((double)ts - (double)gDiag) / count - 1.0);
    }
}

extern "C" void kernel_launch(void* const* d_in, const int* in_sizes, int n_in,
                              void* d_out, int out_size) {
    const float* z_list = (const float*)d_in[0];
    // d_in[1] (z_avg) is ignored — reference recomputes it from z_list.
    (void)in_sizes; (void)n_in; (void)out_size;
    float* out = (float*)d_out;

    init_kernel<<<1, DD>>>();
    main_kernel<<<NN, TPB>>>(z_list);
    final_kernel<<<1, DD>>>(out);
}

// round 4
// speedup vs baseline: 3.2869x; 3.2869x over previous
#include <cuda_runtime.h>
#include <math.h>

// Problem constants
#define PP 20
#define NN 1024
#define DD 512
#define TPB 128          // main kernel: thread t owns d-values [4t, 4t+3]
#define NWARP (TPB / 32)
#define NS 8             // atomic slot count (contention reduction)
#define EPS 1e-8f

// Persistent accumulators. Zero at module load; final_kernel re-zeroes them
// after consuming, so every graph replay sees zeros deterministically.
__device__ float gS[NS][DD];     // slot-partial of S[d] = sum_n an[n][d]
__device__ float gT[NS][DD];     // slot-partial of T[d] = sum_{p,n} zn[p][n][d]
__device__ float gDiag[NS];      // slot-partial of sum_n (sum_p zn_p) . an

// One block per column n.
// Phase 1: stream 20 rows (float4/thread), accumulate avg and 20 norm partials.
//          Block-reduce 21 sums -> 1/max(norm,eps) for avg and each z_p.
// Phase 2: reload the same rows (L2-resident: whole input is 40MB < L2),
//          accumulate zn = sum_p z_p/||z_p||.
//          diag_n = zn . an  (dot is linear -> no per-p dot reductions needed).
// Accumulate an, zn, diag into slotted global atomics.
__global__ __launch_bounds__(TPB) void main_kernel(const float* __restrict__ z) {
    const int n    = blockIdx.x;
    const int t    = threadIdx.x;
    const int wid  = t >> 5;
    const int lane = t & 31;
    const int slot = n & (NS - 1);
    const int d0   = t * 4;

    const size_t stride = (size_t)NN * DD / 4;   // float4 stride between patches
    const float4* base =
        reinterpret_cast<const float4*>(z) + (size_t)n * (DD / 4) + t;

    // ---- phase 1: avg + norm partials (20 independent loads in flight) ----
    float4 avg = make_float4(0.f, 0.f, 0.f, 0.f);
    float s[21];
    #pragma unroll
    for (int p = 0; p < PP; ++p) {
        float4 v = base[(size_t)p * stride];
        avg.x += v.x; avg.y += v.y; avg.z += v.z; avg.w += v.w;
        s[p] = v.x * v.x + v.y * v.y + v.z * v.z + v.w * v.w;
    }
    const float invP = 1.0f / (float)PP;
    avg.x *= invP; avg.y *= invP; avg.z *= invP; avg.w *= invP;
    s[20] = avg.x * avg.x + avg.y * avg.y + avg.z * avg.z + avg.w * avg.w;

    // ---- block-reduce the 21 sums ----
    #pragma unroll
    for (int i = 0; i < 21; ++i) {
        float v = s[i];
        #pragma unroll
        for (int o = 16; o > 0; o >>= 1)
            v += __shfl_xor_sync(0xffffffffu, v, o);
        s[i] = v;
    }

    __shared__ float wp[NWARP][21];   // warp-major: lane0 writes contiguous run
    if (lane == 0) {
        #pragma unroll
        for (int i = 0; i < 21; ++i) wp[wid][i] = s[i];
    }
    __syncthreads();

    __shared__ float inv[21];   // [p]=1/max(||z_p||,eps), [20]=1/max(||avg||,eps)
    if (t < 21) {
        float v = 0.f;
        #pragma unroll
        for (int w = 0; w < NWARP; ++w) v += wp[w][t];
        inv[t] = 1.0f / fmaxf(sqrtf(v), EPS);
    }
    __syncthreads();

    // ---- phase 2: reload rows (L2 hit), accumulate zn ----
    float4 zn = make_float4(0.f, 0.f, 0.f, 0.f);
    #pragma unroll
    for (int p = 0; p < PP; ++p) {
        float4 v = base[(size_t)p * stride];
        const float ip = inv[p];
        zn.x += v.x * ip; zn.y += v.y * ip;
        zn.z += v.z * ip; zn.w += v.w * ip;
    }

    const float inv_avg = inv[20];
    const float an0 = avg.x * inv_avg, an1 = avg.y * inv_avg;
    const float an2 = avg.z * inv_avg, an3 = avg.w * inv_avg;

    // diag_n partial: zn . an
    float dsum = zn.x * an0 + zn.y * an1 + zn.z * an2 + zn.w * an3;
    #pragma unroll
    for (int o = 16; o > 0; o >>= 1)
        dsum += __shfl_xor_sync(0xffffffffu, dsum, o);

    __shared__ float wdg[NWARP];
    if (lane == 0) wdg[wid] = dsum;

    // slotted global accumulation (128 updates per address)
    atomicAdd(&gS[slot][d0 + 0], an0);
    atomicAdd(&gS[slot][d0 + 1], an1);
    atomicAdd(&gS[slot][d0 + 2], an2);
    atomicAdd(&gS[slot][d0 + 3], an3);
    atomicAdd(&gT[slot][d0 + 0], zn.x);
    atomicAdd(&gT[slot][d0 + 1], zn.y);
    atomicAdd(&gT[slot][d0 + 2], zn.z);
    atomicAdd(&gT[slot][d0 + 3], zn.w);

    __syncthreads();
    if (t == 0) {
        float dg = 0.f;
        #pragma unroll
        for (int w = 0; w < NWARP; ++w) dg += wdg[w];
        atomicAdd(&gDiag[slot], dg);
    }
}

// Single block, 512 threads: result = (T.S - diag)/count - 1, then re-zero
// the accumulators so the next graph replay starts clean.
__global__ void final_kernel(float* __restrict__ out) {
    const int t    = threadIdx.x;  // one per d
    const int wid  = t >> 5;
    const int lane = t & 31;

    float S = 0.f, T = 0.f;
    #pragma unroll
    for (int sl = 0; sl < NS; ++sl) { S += gS[sl][t]; T += gT[sl][t]; }

    __shared__ float sdg[NS];
    if (t < NS) sdg[t] = gDiag[t];

    float v = S * T;
    #pragma unroll
    for (int o = 16; o > 0; o >>= 1)
        v += __shfl_xor_sync(0xffffffffu, v, o);

    __shared__ float w[16];
    if (lane == 0) w[wid] = v;
    __syncthreads();

    // re-zero for the next replay (sdg snapshot already taken)
    #pragma unroll
    for (int sl = 0; sl < NS; ++sl) { gS[sl][t] = 0.f; gT[sl][t] = 0.f; }
    if (t < NS) gDiag[t] = 0.f;

    if (t == 0) {
        float ts = 0.f;
        #pragma unroll
        for (int i = 0; i < 16; ++i) ts += w[i];
        float dg = 0.f;
        #pragma unroll
        for (int i = 0; i < NS; ++i) dg += sdg[i];
        const double count = 20.0 * 1024.0 * 1023.0;
        out[0] = (float)(((double)ts - (double)dg) / count - 1.0);
    }
}

extern "C" void kernel_launch(void* const* d_in, const int* in_sizes, int n_in,
                              void* d_out, int out_size) {
    const float* z_list = (const float*)d_in[0];
    // d_in[1] (z_avg) ignored — reference recomputes it from z_list.
    (void)in_sizes; (void)n_in; (void)out_size;
    float* out = (float*)d_out;

    main_kernel<<<NN, TPB>>>(z_list);
    final_kernel<<<1, DD>>>(out);
}